// round 13
// baseline (speedup 1.0000x reference)
#include <cuda_runtime.h>
#include <cuda_fp16.h>
#include <cstdint>
#include <math.h>

#define CIN   64
#define COUT  128
#define HH    224
#define WW    224
#define OH    222
#define OW    222

#define TPX    16          // output px per tile (x)
#define TROWS  8           // output rows per tile (y)
#define INROWS 10          // staged input rows = TROWS + 2
#define PXST   18          // staged px per row = TPX + 2
#define SLAB_STRIDE 3072   // bytes per input row slab

#define BPC0   4           // batches in chunk 0
#define BPC1   12          // batches in chunk 1

// ---------------- global scratch ----------------
__device__ __half g_xh[(size_t)16 * HH * WW * CIN];
__device__ uint4 g_Wfrag[9 * 4 * 8 * 32];

// ---- fused prep: weight shuffle (chunk 0 only) + x transpose/convert ----
#define TSTR 72
__global__ __launch_bounds__(256)
void prep_all(const float* __restrict__ x, const float* __restrict__ w, int zoff) {
    __shared__ __half sT[64 * TSTR];
    const int b   = zoff + blockIdx.z;
    const int y   = blockIdx.y;
    const int px0 = blockIdx.x * 64;
    const int t   = threadIdx.x;
    const int wid = t >> 5, lane = t & 31;

    if (zoff == 0 && blockIdx.z == 0 && blockIdx.x == 0 && y < 9) {
#pragma unroll
        for (int rep = 0; rep < 4; rep++) {
            int i = (y * 4 + rep) * 256 + t;
            int ln   = i & 31;
            int mblk = (i >> 5) & 7;
            int q    = i >> 8;
            int ks   = q & 3;
            int tap  = q >> 2;
            int kh = tap / 3, kw = tap - kh * 3;
            int r  = ln >> 2;
            int k0 = ks * 16 + (ln & 3) * 2;
            uint32_t words[4];
#pragma unroll
            for (int wi = 0; wi < 4; wi++) {
                int co = mblk * 16 + r + (wi & 1) * 8;
                int kk = k0 + (wi >> 1) * 8;
                uint32_t packed = 0;
#pragma unroll
                for (int j = 0; j < 2; j++) {
                    float v = w[((co * CIN + (kk + j)) * 3 + kh) * 3 + kw];
                    packed |= (uint32_t)__half_as_ushort(__float2half(v)) << (16 * j);
                }
                words[wi] = packed;
            }
            g_Wfrag[i] = make_uint4(words[0], words[1], words[2], words[3]);
        }
    }

    const int px = (wid & 1) * 32 + lane;
    const int ip = px0 + px;
    const bool okx = ip < WW;
    const int cib = wid >> 1;
#pragma unroll
    for (int k = 0; k < 16; k++) {
        int ci = cib + k * 4;
        float v = okx ? __ldg(&x[(((size_t)b * CIN + ci) * HH + y) * WW + ip]) : 0.0f;
        sT[px * TSTR + ci] = __float2half(v);
    }
    __syncthreads();

    for (int c = t; c < 512; c += 256) {
        int pxw = c >> 3, cig = c & 7;
        int ipw = px0 + pxw;
        if (ipw < WW) {
            uint4 val = *(const uint4*)&sT[pxw * TSTR + cig * 8];
            *(uint4*)((char*)g_xh + (((size_t)(b * HH + y) * WW + ipw) << 7) + (cig << 4)) = val;
        }
    }
}

// ---------------- helpers ----------------
__device__ __forceinline__ uint32_t smem_u32(const void* p) {
    uint32_t a;
    asm("{ .reg .u64 t; cvta.to.shared.u64 t, %1; cvt.u32.u64 %0, t; }" : "=r"(a) : "l"(p));
    return a;
}
__device__ __forceinline__ uint32_t swz(uint32_t off) { return off ^ ((off >> 3) & 0x70); }

__device__ __forceinline__ void ldsm4(uint32_t& r0, uint32_t& r1, uint32_t& r2, uint32_t& r3, uint32_t addr) {
    asm volatile("ldmatrix.sync.aligned.m8n8.x4.shared.b16 {%0, %1, %2, %3}, [%4];"
        : "=r"(r0), "=r"(r1), "=r"(r2), "=r"(r3) : "r"(addr));
}
__device__ __forceinline__ void mma16816(float* d, const uint4& a, uint32_t b0, uint32_t b1) {
    asm volatile("mma.sync.aligned.m16n8k16.row.col.f32.f16.f16.f32 "
        "{%0, %1, %2, %3}, {%4, %5, %6, %7}, {%8, %9}, {%0, %1, %2, %3};"
        : "+f"(d[0]), "+f"(d[1]), "+f"(d[2]), "+f"(d[3])
        : "r"(a.x), "r"(a.y), "r"(a.z), "r"(a.w), "r"(b0), "r"(b1));
}
__device__ __forceinline__ void cp16(uint32_t dst, const void* src, int sz) {
    asm volatile("cp.async.cg.shared.global [%0], [%1], 16, %2;"
        :: "r"(dst), "l"(src), "r"(sz) : "memory");
}

#define OFF_MIN (INROWS * SLAB_STRIDE)            // 30720
#define SMEM_BYTES (OFF_MIN + 1024 + 1024)

__global__ __launch_bounds__(256, 2)
void conv_mma_kernel(const float* __restrict__ bias,
                     float* __restrict__ out, int zoff) {
    extern __shared__ char smem_raw[];
    uint32_t sb = (smem_u32(smem_raw) + 1023u) & ~1023u;

    const int tid  = threadIdx.x;
    const int wid  = tid >> 5;
    const int lane = tid & 31;
    const int b    = zoff + blockIdx.z;
    const int oy0  = blockIdx.y * TROWS;
    const int x0   = blockIdx.x * TPX;

    const int warpM = wid & 1;
    const int warpN = wid >> 1;

    for (int g = 0; g < INROWS; g++) {
        int y = oy0 + g;
#pragma unroll 1
        for (int c = tid; c < PXST * 8; c += 256) {
            int px  = c >> 3;
            int cig = c & 7;
            int ix  = x0 + px;
            bool ok = (y < HH) && (ix < WW);
            const char* src = (const char*)g_xh +
                (ok ? ((((size_t)(b * HH + y) * WW + ix) << 7) + ((size_t)cig << 4)) : 0);
            uint32_t dst = sb + (uint32_t)(g * SLAB_STRIDE)
                         + (uint32_t)(px * 128 + ((cig ^ (px & 7)) << 4));
            cp16(dst, src, ok ? 16 : 0);
        }
        asm volatile("cp.async.commit_group;" ::: "memory");
    }

    float acc[4][4][4];
#pragma unroll
    for (int m = 0; m < 4; m++) {
        int r_co = warpM * 64 + m * 16 + (lane >> 2);
        float b0 = __ldg(&bias[r_co]);
        float b1 = __ldg(&bias[r_co + 8]);
#pragma unroll
        for (int f = 0; f < 4; f++) {
            acc[m][f][0] = b0; acc[m][f][1] = b0;
            acc[m][f][2] = b1; acc[m][f][3] = b1;
        }
    }

    const uint4* gw = g_Wfrag;
    const int pxl     = lane & 7;
    const int fhalf   = (lane >> 4) & 1;
    const int kb_lane = ((lane >> 3) & 1) * 16;
    const int awoff   = warpM * 4;

#pragma unroll
    for (int kh = 0; kh < 3; kh++) {
        if (kh == 0)      asm volatile("cp.async.wait_group 2;" ::: "memory");
        else if (kh == 1) asm volatile("cp.async.wait_group 1;" ::: "memory");
        else              asm volatile("cp.async.wait_group 0;" ::: "memory");
        __syncthreads();

        const uint32_t row0 = sb + (uint32_t)((2 * warpN + kh) * SLAB_STRIDE);
#pragma unroll
        for (int kw = 0; kw < 3; kw++) {
            const int tap = kh * 3 + kw;
#pragma unroll
            for (int ks = 0; ks < 4; ks++) {
                uint4 A[4];
                const int base = (tap * 4 + ks) * 8;
#pragma unroll
                for (int m = 0; m < 4; m++)
                    A[m] = __ldg(&gw[(base + awoff + m) * 32 + lane]);

                uint32_t B[8];
#pragma unroll
                for (int h = 0; h < 2; h++) {
                    uint32_t off = swz((uint32_t)((pxl + fhalf * 8 + kw) * 128 + kb_lane + ks * 32));
                    ldsm4(B[h*4+0], B[h*4+1], B[h*4+2], B[h*4+3],
                          row0 + (uint32_t)(h * SLAB_STRIDE) + off);
                }
#pragma unroll
                for (int m = 0; m < 4; m++) {
#pragma unroll
                    for (int f = 0; f < 4; f++)
                        mma16816(acc[m][f], A[m], B[f*2], B[f*2+1]);
                }
            }
        }
    }

    float* sMin = (float*)(smem_raw + (sb - smem_u32(smem_raw)) + OFF_MIN);

#pragma unroll
    for (int f = 0; f < 4; f++) {
        float v0 = __int_as_float(0x7f800000), v1 = v0;
#pragma unroll
        for (int m = 0; m < 4; m++) {
            v0 = fminf(v0, fminf(acc[m][f][0], acc[m][f][2]));
            v1 = fminf(v1, fminf(acc[m][f][1], acc[m][f][3]));
        }
#pragma unroll
        for (int off = 4; off < 32; off <<= 1) {
            v0 = fminf(v0, __shfl_xor_sync(0xffffffffu, v0, off));
            v1 = fminf(v1, __shfl_xor_sync(0xffffffffu, v1, off));
        }
        if ((lane >> 2) == 0) {
            int r_loc = 2 * warpN + (f >> 1);
            int px    = (f & 1) * 8 + (lane & 3) * 2;
            int idx   = r_loc * TPX + px;
            sMin[warpM * 128 + idx]     = v0;
            sMin[warpM * 128 + idx + 1] = v1;
        }
    }
    __syncthreads();

    if (tid < 128) {
        int r = tid >> 4, c = tid & 15;
        int orow = oy0 + r, ocol = x0 + c;
        if (orow < OH && ocol < OW) {
            float m = fminf(sMin[tid], sMin[128 + tid]);
            out[((size_t)b * OH + orow) * OW + ocol] = tanhf(tanhf(m));
        }
    }
}

extern "C" void kernel_launch(void* const* d_in, const int* in_sizes, int n_in,
                              void* d_out, int out_size) {
    const float* x    = (const float*)d_in[0];
    const float* w    = (const float*)d_in[1];
    const float* bias = (const float*)d_in[2];
    float* out = (float*)d_out;

    // lazily created side stream + events (host handles only; no device mem).
    static cudaStream_t s2 = nullptr;
    static cudaEvent_t evP0, evP1, evJ;
    if (s2 == nullptr) {
        // EQUAL priority to the capture stream: dispatch round-robins between
        // prep (DRAM-bound) and conv (tensor-bound) grids instead of starving one.
        cudaStreamCreateWithFlags(&s2, cudaStreamNonBlocking);
        cudaEventCreateWithFlags(&evP0, cudaEventDisableTiming);
        cudaEventCreateWithFlags(&evP1, cudaEventDisableTiming);
        cudaEventCreateWithFlags(&evJ,  cudaEventDisableTiming);
        cudaFuncSetAttribute(conv_mma_kernel, cudaFuncAttributeMaxDynamicSharedMemorySize, SMEM_BYTES);
    }

    // enqueue BOTH prep chunks first (older grids get fair dispatch), then convs.
    prep_all<<<dim3(4, HH, BPC0), 256>>>(x, w, 0);
    cudaEventRecord(evP0, 0);
    prep_all<<<dim3(4, HH, BPC1), 256>>>(x, w, BPC0);
    cudaEventRecord(evP1, 0);

    cudaStreamWaitEvent(s2, evP0, 0);
    conv_mma_kernel<<<dim3(14, 28, BPC0), 256, SMEM_BYTES, s2>>>(bias, out, 0);
    cudaStreamWaitEvent(s2, evP1, 0);
    conv_mma_kernel<<<dim3(14, 28, BPC1), 256, SMEM_BYTES, s2>>>(bias, out, BPC0);

    cudaEventRecord(evJ, s2);
    cudaStreamWaitEvent(0, evJ, 0);
}

// round 14
// speedup vs baseline: 1.0193x; 1.0193x over previous
#include <cuda_runtime.h>
#include <cuda_fp16.h>
#include <cstdint>
#include <math.h>

#define CIN   64
#define COUT  128
#define HH    224
#define WW    224
#define OH    222
#define OW    222

#define TPX    16          // output px per tile (x)
#define TROWS  8           // output rows per tile (y)
#define PXST   18          // staged px per row = TPX + 2
#define SLAB_STRIDE 3072   // bytes per input row slab

// ---------------- global scratch ----------------
__device__ __half g_xh[(size_t)16 * HH * WW * CIN];
__device__ uint4 g_Wfrag[9 * 4 * 8 * 32];

// ---- fused prep: weight shuffle (9 blocks) + x transpose/convert ----
#define TSTR 72
__global__ __launch_bounds__(256)
void prep_all(const float* __restrict__ x, const float* __restrict__ w) {
    __shared__ __half sT[64 * TSTR];
    const int b   = blockIdx.z;
    const int y   = blockIdx.y;
    const int px0 = blockIdx.x * 64;
    const int t   = threadIdx.x;
    const int wid = t >> 5, lane = t & 31;

    if (b == 0 && blockIdx.x == 0 && y < 9) {
#pragma unroll
        for (int rep = 0; rep < 4; rep++) {
            int i = (y * 4 + rep) * 256 + t;
            int ln   = i & 31;
            int mblk = (i >> 5) & 7;
            int q    = i >> 8;
            int ks   = q & 3;
            int tap  = q >> 2;
            int kh = tap / 3, kw = tap - kh * 3;
            int r  = ln >> 2;
            int k0 = ks * 16 + (ln & 3) * 2;
            uint32_t words[4];
#pragma unroll
            for (int wi = 0; wi < 4; wi++) {
                int co = mblk * 16 + r + (wi & 1) * 8;
                int kk = k0 + (wi >> 1) * 8;
                uint32_t packed = 0;
#pragma unroll
                for (int j = 0; j < 2; j++) {
                    float v = w[((co * CIN + (kk + j)) * 3 + kh) * 3 + kw];
                    packed |= (uint32_t)__half_as_ushort(__float2half(v)) << (16 * j);
                }
                words[wi] = packed;
            }
            g_Wfrag[i] = make_uint4(words[0], words[1], words[2], words[3]);
        }
    }

    const int px = (wid & 1) * 32 + lane;
    const int ip = px0 + px;
    const bool okx = ip < WW;
    const int cib = wid >> 1;
#pragma unroll
    for (int k = 0; k < 16; k++) {
        int ci = cib + k * 4;
        float v = okx ? __ldg(&x[(((size_t)b * CIN + ci) * HH + y) * WW + ip]) : 0.0f;
        sT[px * TSTR + ci] = __float2half(v);
    }
    __syncthreads();

    for (int c = t; c < 512; c += 256) {
        int pxw = c >> 3, cig = c & 7;
        int ipw = px0 + pxw;
        if (ipw < WW) {
            uint4 val = *(const uint4*)&sT[pxw * TSTR + cig * 8];
            *(uint4*)((char*)g_xh + (((size_t)(b * HH + y) * WW + ipw) << 7) + (cig << 4)) = val;
        }
    }
}

// ---------------- helpers ----------------
__device__ __forceinline__ uint32_t smem_u32(const void* p) {
    uint32_t a;
    asm("{ .reg .u64 t; cvta.to.shared.u64 t, %1; cvt.u32.u64 %0, t; }" : "=r"(a) : "l"(p));
    return a;
}
__device__ __forceinline__ void ldsm4(uint32_t& r0, uint32_t& r1, uint32_t& r2, uint32_t& r3, uint32_t addr) {
    asm volatile("ldmatrix.sync.aligned.m8n8.x4.shared.b16 {%0, %1, %2, %3}, [%4];"
        : "=r"(r0), "=r"(r1), "=r"(r2), "=r"(r3) : "r"(addr));
}
__device__ __forceinline__ void mma16816(float* d, const uint4& a, uint32_t b0, uint32_t b1) {
    asm volatile("mma.sync.aligned.m16n8k16.row.col.f32.f16.f16.f32 "
        "{%0, %1, %2, %3}, {%4, %5, %6, %7}, {%8, %9}, {%0, %1, %2, %3};"
        : "+f"(d[0]), "+f"(d[1]), "+f"(d[2]), "+f"(d[3])
        : "r"(a.x), "r"(a.y), "r"(a.z), "r"(a.w), "r"(b0), "r"(b1));
}
__device__ __forceinline__ void cp16(uint32_t dst, const void* src, int sz) {
    asm volatile("cp.async.cg.shared.global [%0], [%1], 16, %2;"
        :: "r"(dst), "l"(src), "r"(sz) : "memory");
}
__device__ __forceinline__ uint32_t swz(uint32_t off) { return off ^ ((off >> 3) & 0x70); }

// smem: 4 pairs x 4 row-slabs (private), then sMin
#define OFF_MIN (16 * SLAB_STRIDE)                // 49152
#define SMEM_BYTES (OFF_MIN + 1024 + 1024)        // 51200

__global__ __launch_bounds__(256, 2)
void conv_mma_kernel(const float* __restrict__ bias,
                     float* __restrict__ out) {
    extern __shared__ char smem_raw[];
    uint32_t sb = (smem_u32(smem_raw) + 1023u) & ~1023u;

    const int tid  = threadIdx.x;
    const int wid  = tid >> 5;
    const int lane = tid & 31;
    const int b    = blockIdx.z;
    const int oy0  = blockIdx.y * TROWS;
    const int x0   = blockIdx.x * TPX;

    const int warpM = wid & 1;       // co half
    const int pair  = wid >> 1;      // warpN: output rows 2*pair, 2*pair+1

    const uint32_t pairbase = sb + (uint32_t)(pair * 4 * SLAB_STRIDE);

    // ---- per-pair staging: local rows j=0..3 are input rows oy0+2*pair+j.
    // warpM=0 stages j={0,2}; warpM=1 stages j={1,3}. One commit group per row.
#pragma unroll
    for (int s = 0; s < 2; s++) {
        const int j = warpM + 2 * s;
        const int y = oy0 + 2 * pair + j;
#pragma unroll 1
        for (int c = lane; c < PXST * 8; c += 32) {   // 144 chunks / 32 lanes
            int px  = c >> 3;
            int cig = c & 7;
            int ix  = x0 + px;
            bool ok = (y < HH) && (ix < WW);
            const char* src = (const char*)g_xh +
                (ok ? ((((size_t)(b * HH + y) * WW + ix) << 7) + ((size_t)cig << 4)) : 0);
            uint32_t dst = pairbase + (uint32_t)(j * SLAB_STRIDE)
                         + (uint32_t)(px * 128 + ((cig ^ (px & 7)) << 4));
            cp16(dst, src, ok ? 16 : 0);
        }
        asm volatile("cp.async.commit_group;" ::: "memory");
    }

    // ---- accumulators, init = bias[co] ----
    float acc[4][4][4];
#pragma unroll
    for (int m = 0; m < 4; m++) {
        int r_co = warpM * 64 + m * 16 + (lane >> 2);
        float b0 = __ldg(&bias[r_co]);
        float b1 = __ldg(&bias[r_co + 8]);
#pragma unroll
        for (int f = 0; f < 4; f++) {
            acc[m][f][0] = b0; acc[m][f][1] = b0;
            acc[m][f][2] = b1; acc[m][f][3] = b1;
        }
    }

    const uint4* gw = g_Wfrag;
    const int pxl     = lane & 7;
    const int fhalf   = (lane >> 4) & 1;
    const int kb_lane = ((lane >> 3) & 1) * 16;
    const int awoff   = warpM * 4;
    const int barid   = pair + 1;

#pragma unroll
    for (int kh = 0; kh < 3; kh++) {
        // per-warp wait on OWN groups, then pair-scoped barrier publishes both.
        // groups committed: g0 = row j=warpM, g1 = row j=warpM+2.
        if (kh == 0) {
            asm volatile("cp.async.wait_group 1;" ::: "memory");   // need j=0,1: own g0
        } else if (kh == 1) {
            if (warpM == 0) { asm volatile("cp.async.wait_group 0;" ::: "memory"); } // need j=2 (own g1)
            else            { asm volatile("cp.async.wait_group 1;" ::: "memory"); } // need j=1 (own g0)
        } else {
            asm volatile("cp.async.wait_group 0;" ::: "memory");   // need j=2,3: own g1
        }
        asm volatile("bar.sync %0, %1;" :: "r"(barid), "r"(64) : "memory");

        const uint32_t row0 = pairbase + (uint32_t)(kh * SLAB_STRIDE);
#pragma unroll
        for (int kw = 0; kw < 3; kw++) {
            const int tap = kh * 3 + kw;
#pragma unroll
            for (int ks = 0; ks < 4; ks++) {
                uint4 A[4];
                const int base = (tap * 4 + ks) * 8;
#pragma unroll
                for (int m = 0; m < 4; m++)
                    A[m] = __ldg(&gw[(base + awoff + m) * 32 + lane]);

                uint32_t B[8];
#pragma unroll
                for (int h = 0; h < 2; h++) {
                    uint32_t off = swz((uint32_t)((pxl + fhalf * 8 + kw) * 128 + kb_lane + ks * 32));
                    ldsm4(B[h*4+0], B[h*4+1], B[h*4+2], B[h*4+3],
                          row0 + (uint32_t)(h * SLAB_STRIDE) + off);
                }
#pragma unroll
                for (int m = 0; m < 4; m++) {
#pragma unroll
                    for (int f = 0; f < 4; f++)
                        mma16816(acc[m][f], A[m], B[f*2], B[f*2+1]);
                }
            }
        }
    }

    // ---- epilogue: min over co ----
    float* sMin = (float*)(smem_raw + (sb - smem_u32(smem_raw)) + OFF_MIN);

#pragma unroll
    for (int f = 0; f < 4; f++) {
        float v0 = __int_as_float(0x7f800000), v1 = v0;
#pragma unroll
        for (int m = 0; m < 4; m++) {
            v0 = fminf(v0, fminf(acc[m][f][0], acc[m][f][2]));
            v1 = fminf(v1, fminf(acc[m][f][1], acc[m][f][3]));
        }
#pragma unroll
        for (int off = 4; off < 32; off <<= 1) {
            v0 = fminf(v0, __shfl_xor_sync(0xffffffffu, v0, off));
            v1 = fminf(v1, __shfl_xor_sync(0xffffffffu, v1, off));
        }
        if ((lane >> 2) == 0) {
            int r_loc = 2 * pair + (f >> 1);
            int px    = (f & 1) * 8 + (lane & 3) * 2;
            int idx   = r_loc * TPX + px;
            sMin[warpM * 128 + idx]     = v0;
            sMin[warpM * 128 + idx + 1] = v1;
        }
    }
    __syncthreads();

    if (tid < 128) {
        int r = tid >> 4, c = tid & 15;
        int orow = oy0 + r, ocol = x0 + c;
        if (orow < OH && ocol < OW) {
            float m = fminf(sMin[tid], sMin[128 + tid]);
            out[((size_t)b * OH + orow) * OW + ocol] = tanhf(tanhf(m));
        }
    }
}

extern "C" void kernel_launch(void* const* d_in, const int* in_sizes, int n_in,
                              void* d_out, int out_size) {
    const float* x    = (const float*)d_in[0];
    const float* w    = (const float*)d_in[1];
    const float* bias = (const float*)d_in[2];
    float* out = (float*)d_out;

    prep_all<<<dim3(4, HH, 16), 256>>>(x, w);

    cudaFuncSetAttribute(conv_mma_kernel, cudaFuncAttributeMaxDynamicSharedMemorySize, SMEM_BYTES);
    dim3 grid((OW + TPX - 1) / TPX,      // 14
              (OH + TROWS - 1) / TROWS,  // 28
              16);
    conv_mma_kernel<<<grid, 256, SMEM_BYTES>>>(bias, out);
}